// round 7
// baseline (speedup 1.0000x reference)
#include <cuda_runtime.h>
#include <cuda_fp16.h>
#include <cstdint>

#define B 32
#define N 1024
#define M 1024
#define TOL 0.001f
#define MAX_ITER 50
#define BPB 16                 // blocks per batch
#define GRID (B * BPB)         // 512: 4 blocks/SM via launch_bounds(256,4)
#define TPB 256
#define RPB 64                 // rows per block
#define EM105 2.7536449349747158e-5f   // exp(-10.5): scaled-u init (log_u0 = 0)

// ---------------------------------------------------------------------------
__device__ __half   g_K16[(size_t)B * N * M];     // 64 MB, L2-resident
__device__ float    g_partial[2][GRID * M];       // [parity][(b*BPB+sl)*M + c]
__device__ float    g_vbuf[2][B * M];             // [parity][b*M + c]
__device__ int      g_chgBatch[MAX_ITER * B];
__device__ int      g_change[MAX_ITER];
__device__ int      g_chgCount[MAX_ITER];
__device__ unsigned g_batCount[B * 32];           // padded: one line per batch
__device__ unsigned g_batGen[B * 32];

__global__ void initKernel() {
    int t = threadIdx.x;
    for (int i = t; i < MAX_ITER * B; i += 256) g_chgBatch[i] = 0;
    for (int i = t; i < MAX_ITER; i += 256) { g_change[i] = 0; g_chgCount[i] = 0; }
    for (int i = t; i < B * 32; i += 256) { g_batCount[i] = 0u; g_batGen[i] = 0u; }
}

// exp(10.5 - 20c), c in [0,1): 2^ri * poly(f*ln2). FMA-only, ~1e-8 rel err.
__device__ __forceinline__ float kexp10(float c) {
    float y  = fmaf(c, -28.853900817779268f, 15.148297929334116f);
    int   ri = __float2int_rn(y);
    float x  = (y - (float)ri) * 0.69314718055994531f;
    float p  = 1.9841269841e-4f;
    p = fmaf(p, x, 1.3888888889e-3f);
    p = fmaf(p, x, 8.3333333333e-3f);
    p = fmaf(p, x, 4.1666666667e-2f);
    p = fmaf(p, x, 1.6666666667e-1f);
    p = fmaf(p, x, 0.5f);
    p = fmaf(p, x, 1.0f);
    p = fmaf(p, x, 1.0f);
    return p * __int_as_float((ri + 127) << 23);
}

__device__ __forceinline__ float dot8(uint4 kq, float4 va, float4 vb) {
    float2 f0 = __half22float2(*(__half2*)&kq.x);
    float2 f1 = __half22float2(*(__half2*)&kq.y);
    float2 f2 = __half22float2(*(__half2*)&kq.z);
    float2 f3 = __half22float2(*(__half2*)&kq.w);
    return f0.x*va.x + f0.y*va.y + f1.x*va.z + f1.y*va.w
         + f2.x*vb.x + f2.y*vb.y + f3.x*vb.z + f3.y*vb.w;
}

// Per-batch sense-reversing barrier (16 arrivals on a private cache line).
__device__ __forceinline__ void batchBarrier(int b, unsigned gen) {
    __syncthreads();
    if (threadIdx.x == 0) {
        __threadfence();
        if (atomicAdd(&g_batCount[b * 32], 1u) == BPB - 1) {
            atomicExch(&g_batCount[b * 32], 0u);
            __threadfence();
            atomicExch(&g_batGen[b * 32], gen + 1u);
        } else {
            while (atomicAdd(&g_batGen[b * 32], 0u) < gen + 1u) __nanosleep(32);
        }
        __threadfence();
    }
    __syncthreads();
}

// ---------------------------------------------------------------------------
__global__ void __launch_bounds__(TPB, 4) sinkhornKernel(
    const float* __restrict__ cost, const float* __restrict__ src,
    const float* __restrict__ tgt, float* __restrict__ out) {

    __shared__ float sv[M];          // v for this batch
    __shared__ float sacc[2][M];     // col-partial staging (2 row-subsets)
    __shared__ float suAll[RPB];     // scaled u' for this block's rows
    __shared__ float srow[RPB];      // prologue row sums
    __shared__ float schg[8];
    __shared__ int   schgBits;
    __shared__ int   sbrk;

    const int t    = threadIdx.x;
    const int w    = t >> 5;
    const int lane = t & 31;
    const int blk  = blockIdx.x;
    const int b    = blk >> 4;
    const int sl   = blk & 15;
    const int rowBase = (b << 10) + (sl << 6);
    const size_t elemBase = (size_t)rowBase << 10;

    const float4* Cr  = (const float4*)(cost + elemBase);
    const float4* sv4 = (const float4*)sv;

    if (t < RPB) srow[t] = 0.0f;
    if (t == 0)  schgBits = 0;
    __syncthreads();

    // ---- prologue: convert own 64-row slice (streaming cost reads) + row sums (v0=1) ----
    {
        uint4* Kw = (uint4*)(g_K16 + elemBase);
        #pragma unroll 2
        for (int k = 0; k < 32; ++k) {
            int i = k * TPB + t;                       // uint4 index, 128 per row
            float4 c0 = __ldcs(Cr + 2 * i), c1 = __ldcs(Cr + 2 * i + 1);
            float f0 = kexp10(c0.x), f1 = kexp10(c0.y);
            float f2 = kexp10(c0.z), f3 = kexp10(c0.w);
            float f4 = kexp10(c1.x), f5 = kexp10(c1.y);
            float f6 = kexp10(c1.z), f7 = kexp10(c1.w);
            __half2 h0 = __floats2half2_rn(f0, f1), h1 = __floats2half2_rn(f2, f3);
            __half2 h2 = __floats2half2_rn(f4, f5), h3 = __floats2half2_rn(f6, f7);
            uint4 pk;
            pk.x = *(unsigned*)&h0; pk.y = *(unsigned*)&h1;
            pk.z = *(unsigned*)&h2; pk.w = *(unsigned*)&h3;
            Kw[i] = pk;
            float s = ((f0 + f1) + (f2 + f3)) + ((f4 + f5) + (f6 + f7));
            #pragma unroll
            for (int o = 16; o; o >>= 1) s += __shfl_xor_sync(0xFFFFFFFFu, s, o);
            if (lane == 0) atomicAdd(&srow[i >> 7], s);   // i>>7 uniform in warp
        }
    }
    __syncthreads();
    if (t < RPB) {                    // u1 = (src+eps)/rowsum ; iteration-1 change
        float nu = (__ldg(src + rowBase + t) + 1e-12f) / srow[t];
        suAll[t] = nu;
        atomicMax(&schgBits, __float_as_int(fabsf(logf(nu / EM105))));
    }
    __syncthreads();
    if (t == 0) atomicMax(&g_chgBatch[b], schgBits);      // it = 0 slot

    unsigned gen = 0;
    const int cg = t & 127, rs = t >> 7;

    for (int it = 0; it < MAX_ITER; ++it) {
        float acc[8];
        #pragma unroll
        for (int j = 0; j < 8; ++j) acc[j] = 0.f;
        float chmax = 0.f;

        #pragma unroll
        for (int g = 0; g < 4; ++g) {                     // 16-row groups
            if (it > 0) {
                // --- row dots: warp w handles rows r0, r0+1 ---
                int r0 = (g << 4) + (w << 1);
                const uint4* K0 = (const uint4*)g_K16 + ((size_t)(rowBase + r0) << 7);
                float s0 = 0.f, s1 = 0.f;
                #pragma unroll
                for (int i = 0; i < 4; ++i) {
                    int ci = i * 32 + lane;
                    uint4 ka = K0[ci], kb = K0[128 + ci];
                    float4 va = sv4[2 * ci], vb = sv4[2 * ci + 1];
                    s0 += dot8(ka, va, vb);
                    s1 += dot8(kb, va, vb);
                }
                #pragma unroll
                for (int o = 16; o; o >>= 1) {
                    s0 += __shfl_xor_sync(0xFFFFFFFFu, s0, o);
                    s1 += __shfl_xor_sync(0xFFFFFFFFu, s1, o);
                }
                if (lane == 0) {
                    float o0 = suAll[r0], o1 = suAll[r0 + 1];
                    float n0 = (__ldg(src + rowBase + r0)     + 1e-12f) / s0;
                    float n1 = (__ldg(src + rowBase + r0 + 1) + 1e-12f) / s1;
                    suAll[r0] = n0; suAll[r0 + 1] = n1;
                    chmax = fmaxf(chmax,
                            fmaxf(fabsf(logf(n0 / o0)), fabsf(logf(n1 / o1))));
                }
                __syncthreads();
            }
            // --- col acc: thread (cg,rs): cols cg*8..+7 over 8 rows (L1-hot) ---
            {
                int r0 = (g << 4) + (rs << 3);
                const uint4* Kc = (const uint4*)g_K16
                    + ((size_t)(rowBase + r0) << 7) + cg;
                #pragma unroll
                for (int j = 0; j < 8; ++j) {
                    uint4 kq = Kc[(size_t)j << 7];
                    float uu = suAll[r0 + j];
                    float2 f0 = __half22float2(*(__half2*)&kq.x);
                    float2 f1 = __half22float2(*(__half2*)&kq.y);
                    float2 f2 = __half22float2(*(__half2*)&kq.z);
                    float2 f3 = __half22float2(*(__half2*)&kq.w);
                    acc[0] = fmaf(f0.x, uu, acc[0]);
                    acc[1] = fmaf(f0.y, uu, acc[1]);
                    acc[2] = fmaf(f1.x, uu, acc[2]);
                    acc[3] = fmaf(f1.y, uu, acc[3]);
                    acc[4] = fmaf(f2.x, uu, acc[4]);
                    acc[5] = fmaf(f2.y, uu, acc[5]);
                    acc[6] = fmaf(f3.x, uu, acc[6]);
                    acc[7] = fmaf(f3.y, uu, acc[7]);
                }
            }
        }

        // --- stage, combine subsets, write block partial; push batch change ---
        #pragma unroll
        for (int j = 0; j < 8; ++j) sacc[rs][cg * 8 + j] = acc[j];
        if (lane == 0) schg[w] = chmax;
        __syncthreads();
        {
            float* pp = g_partial[it & 1] + (size_t)blk * M;
            #pragma unroll
            for (int c = t; c < M; c += TPB) pp[c] = sacc[0][c] + sacc[1][c];
        }
        if (t == 0 && it > 0) {
            float m = schg[0];
            #pragma unroll
            for (int i = 1; i < 8; ++i) m = fmaxf(m, schg[i]);
            atomicMax(&g_chgBatch[it * B + b], __float_as_int(m));
        }

        batchBarrier(b, gen); ++gen;

        // leader pushes batch change to global (overlaps v-slice below)
        if (sl == 0 && t == 0) {
            int cb = __ldcg(&g_chgBatch[it * B + b]);
            atomicMax(&g_change[it], cb);
            __threadfence();
            atomicAdd(&g_chgCount[it], 1);
        }
        // --- v-slice: this block owns cols [sl*64, sl*64+64) ---
        if (t < 64) {
            int c = (sl << 6) + t;
            const float* pb = g_partial[it & 1] + (size_t)(b * BPB) * M + c;
            float ssum = 0.f;
            #pragma unroll
            for (int k = 0; k < BPB; ++k) ssum += __ldcg(pb + (size_t)k * M);
            g_vbuf[it & 1][(b << 10) + c] =
                (__ldg(tgt + (b << 10) + c) + 1e-12f) / ssum;
        }

        batchBarrier(b, gen); ++gen;

        // load full v into smem
        {
            const float* vb_ = g_vbuf[it & 1] + (b << 10);
            #pragma unroll
            for (int c = t; c < M; c += TPB) sv[c] = __ldcg(vb_ + c);
        }
        // global convergence decision (poll count, then read value)
        if (t == 0) {
            while (*(volatile int*)&g_chgCount[it] < B) __nanosleep(128);
            sbrk = (__int_as_float(__ldcg(&g_change[it])) < TOL) ? 1 : 0;
        }
        __syncthreads();
        if (sbrk) break;
    }

    // ---- epilogue: T = u' * K16 * v  (K16 from L2, streaming out stores) ----
    {
        const uint4* Kr = (const uint4*)(g_K16 + elemBase);
        float4* Ow = (float4*)(out + elemBase);
        #pragma unroll 2
        for (int k = 0; k < 32; ++k) {
            int i = k * TPB + t;
            uint4 kq = Kr[i];
            float u = suAll[i >> 7];
            float4 va = sv4[(i & 127) * 2], vb = sv4[(i & 127) * 2 + 1];
            float2 f0 = __half22float2(*(__half2*)&kq.x);
            float2 f1 = __half22float2(*(__half2*)&kq.y);
            float2 f2 = __half22float2(*(__half2*)&kq.z);
            float2 f3 = __half22float2(*(__half2*)&kq.w);
            float4 o0, o1;
            o0.x = u * f0.x * va.x;
            o0.y = u * f0.y * va.y;
            o0.z = u * f1.x * va.z;
            o0.w = u * f1.y * va.w;
            o1.x = u * f2.x * vb.x;
            o1.y = u * f2.y * vb.y;
            o1.z = u * f3.x * vb.z;
            o1.w = u * f3.y * vb.w;
            __stcs(Ow + 2 * i,     o0);
            __stcs(Ow + 2 * i + 1, o1);
        }
    }
}

// ---------------------------------------------------------------------------
extern "C" void kernel_launch(void* const* d_in, const int* in_sizes, int n_in,
                              void* d_out, int out_size) {
    const float* cost = (const float*)d_in[0];
    const float* src  = (const float*)d_in[1];
    const float* tgt  = (const float*)d_in[2];
    float* out = (float*)d_out;

    initKernel<<<1, 256>>>();
    sinkhornKernel<<<GRID, TPB>>>(cost, src, tgt, out);
}

// round 9
// speedup vs baseline: 1.0033x; 1.0033x over previous
#include <cuda_runtime.h>
#include <cuda_fp16.h>
#include <cstdint>

#define B 32
#define N 1024
#define M 1024
#define TOL 0.001f
#define MAX_ITER 50
#define BPB 16                 // blocks per batch
#define GRID (B * BPB)         // 512: 4 blocks/SM via launch_bounds(256,4)
#define TPB 256
#define RPB 64                 // rows per block
#define EM105 2.7536449349747158e-5f   // exp(-10.5): scaled-u init (log_u0 = 0)

// ---------------------------------------------------------------------------
__device__ __half   g_K16[(size_t)B * N * M];     // 64 MB, L2-resident
__device__ float    g_partial[2][GRID * M];       // [parity][(b*BPB+sl)*M + c]
__device__ float    g_vbuf[2][B * M];             // [parity][b*M + c]
__device__ int      g_chgBatch[MAX_ITER * B];
__device__ int      g_change[MAX_ITER];
__device__ int      g_chgCount[MAX_ITER];
__device__ unsigned g_batCount[B * 32];           // padded: one line per batch
__device__ unsigned g_batGen[B * 32];

__global__ void initKernel() {
    int t = threadIdx.x;
    for (int i = t; i < MAX_ITER * B; i += 256) g_chgBatch[i] = 0;
    for (int i = t; i < MAX_ITER; i += 256) { g_change[i] = 0; g_chgCount[i] = 0; }
    for (int i = t; i < B * 32; i += 256) { g_batCount[i] = 0u; g_batGen[i] = 0u; }
}

// exp(10.5 - 20c), c in [0,1): 2^ri * poly(f*ln2). FMA-only, ~1e-8 rel err.
__device__ __forceinline__ float kexp10(float c) {
    float y  = fmaf(c, -28.853900817779268f, 15.148297929334116f);
    int   ri = __float2int_rn(y);
    float x  = (y - (float)ri) * 0.69314718055994531f;
    float p  = 1.9841269841e-4f;
    p = fmaf(p, x, 1.3888888889e-3f);
    p = fmaf(p, x, 8.3333333333e-3f);
    p = fmaf(p, x, 4.1666666667e-2f);
    p = fmaf(p, x, 1.6666666667e-1f);
    p = fmaf(p, x, 0.5f);
    p = fmaf(p, x, 1.0f);
    p = fmaf(p, x, 1.0f);
    return p * __int_as_float((ri + 127) << 23);
}

__device__ __forceinline__ float dot8(uint4 kq, float4 va, float4 vb) {
    float2 f0 = __half22float2(*(__half2*)&kq.x);
    float2 f1 = __half22float2(*(__half2*)&kq.y);
    float2 f2 = __half22float2(*(__half2*)&kq.z);
    float2 f3 = __half22float2(*(__half2*)&kq.w);
    return f0.x*va.x + f0.y*va.y + f1.x*va.z + f1.y*va.w
         + f2.x*vb.x + f2.y*vb.y + f3.x*vb.z + f3.y*vb.w;
}

// Per-batch sense-reversing barrier (16 arrivals on a private cache line).
__device__ __forceinline__ void batchBarrier(int b, unsigned gen) {
    __syncthreads();
    if (threadIdx.x == 0) {
        __threadfence();
        if (atomicAdd(&g_batCount[b * 32], 1u) == BPB - 1) {
            atomicExch(&g_batCount[b * 32], 0u);
            __threadfence();
            atomicExch(&g_batGen[b * 32], gen + 1u);
        } else {
            while (atomicAdd(&g_batGen[b * 32], 0u) < gen + 1u) __nanosleep(32);
        }
        __threadfence();
    }
    __syncthreads();
}

// ---------------------------------------------------------------------------
__global__ void __launch_bounds__(TPB, 4) sinkhornKernel(
    const float* __restrict__ cost, const float* __restrict__ src,
    const float* __restrict__ tgt, float* __restrict__ out) {

    __shared__ float sv[M];          // v for this batch
    __shared__ float sacc[2][M];     // col-partial staging (2 row-subsets)
    __shared__ float suAll[RPB];     // scaled u' for this block's rows
    __shared__ float srow[RPB];      // prologue row sums
    __shared__ float schg[8];
    __shared__ int   schgBits;
    __shared__ int   sbrk;

    const int t    = threadIdx.x;
    const int w    = t >> 5;
    const int lane = t & 31;
    const int blk  = blockIdx.x;
    const int b    = blk >> 4;
    const int sl   = blk & 15;
    const int rowBase = (b << 10) + (sl << 6);
    const size_t elemBase = (size_t)rowBase << 10;

    const float4* Cr  = (const float4*)(cost + elemBase);
    const float4* sv4 = (const float4*)sv;

    if (t < RPB) srow[t] = 0.0f;
    if (t == 0)  schgBits = 0;
    __syncthreads();

    // ---- prologue: convert own 64-row slice (streaming cost reads) + row sums (v0=1) ----
    {
        uint4* Kw = (uint4*)(g_K16 + elemBase);
        #pragma unroll 2
        for (int k = 0; k < 32; ++k) {
            int i = k * TPB + t;                       // uint4 index, 128 per row
            float4 c0 = __ldcs(Cr + 2 * i), c1 = __ldcs(Cr + 2 * i + 1);
            float f0 = kexp10(c0.x), f1 = kexp10(c0.y);
            float f2 = kexp10(c0.z), f3 = kexp10(c0.w);
            float f4 = kexp10(c1.x), f5 = kexp10(c1.y);
            float f6 = kexp10(c1.z), f7 = kexp10(c1.w);
            __half2 h0 = __floats2half2_rn(f0, f1), h1 = __floats2half2_rn(f2, f3);
            __half2 h2 = __floats2half2_rn(f4, f5), h3 = __floats2half2_rn(f6, f7);
            uint4 pk;
            pk.x = *(unsigned*)&h0; pk.y = *(unsigned*)&h1;
            pk.z = *(unsigned*)&h2; pk.w = *(unsigned*)&h3;
            Kw[i] = pk;
            float s = ((f0 + f1) + (f2 + f3)) + ((f4 + f5) + (f6 + f7));
            #pragma unroll
            for (int o = 16; o; o >>= 1) s += __shfl_xor_sync(0xFFFFFFFFu, s, o);
            if (lane == 0) atomicAdd(&srow[i >> 7], s);   // i>>7 uniform in warp
        }
    }
    __syncthreads();
    if (t < RPB) {                    // u1 = (src+eps)/rowsum ; iteration-1 change
        float nu = (__ldg(src + rowBase + t) + 1e-12f) / srow[t];
        suAll[t] = nu;
        atomicMax(&schgBits, __float_as_int(fabsf(logf(nu / EM105))));
    }
    __syncthreads();
    if (t == 0) atomicMax(&g_chgBatch[b], schgBits);      // it = 0 slot

    unsigned gen = 0;
    const int cg = t & 127, rs = t >> 7;

    for (int it = 0; it < MAX_ITER; ++it) {
        float acc[8];
        #pragma unroll
        for (int j = 0; j < 8; ++j) acc[j] = 0.f;
        float chmax = 0.f;

        #pragma unroll
        for (int g = 0; g < 4; ++g) {                     // 16-row groups
            if (it > 0) {
                // --- row dots: warp w handles rows r0, r0+1 ---
                int r0 = (g << 4) + (w << 1);
                const uint4* K0 = (const uint4*)g_K16 + ((size_t)(rowBase + r0) << 7);
                float s0 = 0.f, s1 = 0.f;
                #pragma unroll
                for (int i = 0; i < 4; ++i) {
                    int ci = i * 32 + lane;
                    uint4 ka = K0[ci], kb = K0[128 + ci];
                    float4 va = sv4[2 * ci], vb = sv4[2 * ci + 1];
                    s0 += dot8(ka, va, vb);
                    s1 += dot8(kb, va, vb);
                }
                #pragma unroll
                for (int o = 16; o; o >>= 1) {
                    s0 += __shfl_xor_sync(0xFFFFFFFFu, s0, o);
                    s1 += __shfl_xor_sync(0xFFFFFFFFu, s1, o);
                }
                if (lane == 0) {
                    float o0 = suAll[r0], o1 = suAll[r0 + 1];
                    float n0 = (__ldg(src + rowBase + r0)     + 1e-12f) / s0;
                    float n1 = (__ldg(src + rowBase + r0 + 1) + 1e-12f) / s1;
                    suAll[r0] = n0; suAll[r0 + 1] = n1;
                    chmax = fmaxf(chmax,
                            fmaxf(fabsf(logf(n0 / o0)), fabsf(logf(n1 / o1))));
                }
                __syncthreads();
            }
            // --- col acc: thread (cg,rs): cols cg*8..+7 over 8 rows (L1-hot) ---
            {
                int r0 = (g << 4) + (rs << 3);
                const uint4* Kc = (const uint4*)g_K16
                    + ((size_t)(rowBase + r0) << 7) + cg;
                #pragma unroll
                for (int j = 0; j < 8; ++j) {
                    uint4 kq = Kc[(size_t)j << 7];
                    float uu = suAll[r0 + j];
                    float2 f0 = __half22float2(*(__half2*)&kq.x);
                    float2 f1 = __half22float2(*(__half2*)&kq.y);
                    float2 f2 = __half22float2(*(__half2*)&kq.z);
                    float2 f3 = __half22float2(*(__half2*)&kq.w);
                    acc[0] = fmaf(f0.x, uu, acc[0]);
                    acc[1] = fmaf(f0.y, uu, acc[1]);
                    acc[2] = fmaf(f1.x, uu, acc[2]);
                    acc[3] = fmaf(f1.y, uu, acc[3]);
                    acc[4] = fmaf(f2.x, uu, acc[4]);
                    acc[5] = fmaf(f2.y, uu, acc[5]);
                    acc[6] = fmaf(f3.x, uu, acc[6]);
                    acc[7] = fmaf(f3.y, uu, acc[7]);
                }
            }
        }

        // --- stage, combine subsets, write block partial; push batch change ---
        #pragma unroll
        for (int j = 0; j < 8; ++j) sacc[rs][cg * 8 + j] = acc[j];
        if (lane == 0) schg[w] = chmax;
        __syncthreads();
        {
            float* pp = g_partial[it & 1] + (size_t)blk * M;
            #pragma unroll
            for (int c = t; c < M; c += TPB) pp[c] = sacc[0][c] + sacc[1][c];
        }
        if (t == 0 && it > 0) {
            float m = schg[0];
            #pragma unroll
            for (int i = 1; i < 8; ++i) m = fmaxf(m, schg[i]);
            atomicMax(&g_chgBatch[it * B + b], __float_as_int(m));
        }

        batchBarrier(b, gen); ++gen;

        // leader pushes batch change to global (overlaps v-slice below)
        if (sl == 0 && t == 0) {
            int cb = __ldcg(&g_chgBatch[it * B + b]);
            atomicMax(&g_change[it], cb);
            __threadfence();
            atomicAdd(&g_chgCount[it], 1);
        }
        // --- v-slice: this block owns cols [sl*64, sl*64+64) ---
        if (t < 64) {
            int c = (sl << 6) + t;
            const float* pb = g_partial[it & 1] + (size_t)(b * BPB) * M + c;
            float ssum = 0.f;
            #pragma unroll
            for (int k = 0; k < BPB; ++k) ssum += __ldcg(pb + (size_t)k * M);
            g_vbuf[it & 1][(b << 10) + c] =
                (__ldg(tgt + (b << 10) + c) + 1e-12f) / ssum;
        }

        batchBarrier(b, gen); ++gen;

        // load full v into smem
        {
            const float* vb_ = g_vbuf[it & 1] + (b << 10);
            #pragma unroll
            for (int c = t; c < M; c += TPB) sv[c] = __ldcg(vb_ + c);
        }
        // global convergence decision (poll count, then read value)
        if (t == 0) {
            while (*(volatile int*)&g_chgCount[it] < B) __nanosleep(128);
            sbrk = (__int_as_float(__ldcg(&g_change[it])) < TOL) ? 1 : 0;
        }
        __syncthreads();
        if (sbrk) break;
    }

    // ---- epilogue: T = u' * K16 * v  (K16 from L2, streaming out stores) ----
    {
        const uint4* Kr = (const uint4*)(g_K16 + elemBase);
        float4* Ow = (float4*)(out + elemBase);
        #pragma unroll 2
        for (int k = 0; k < 32; ++k) {
            int i = k * TPB + t;
            uint4 kq = Kr[i];
            float u = suAll[i >> 7];
            float4 va = sv4[(i & 127) * 2], vb = sv4[(i & 127) * 2 + 1];
            float2 f0 = __half22float2(*(__half2*)&kq.x);
            float2 f1 = __half22float2(*(__half2*)&kq.y);
            float2 f2 = __half22float2(*(__half2*)&kq.z);
            float2 f3 = __half22float2(*(__half2*)&kq.w);
            float4 o0, o1;
            o0.x = u * f0.x * va.x;
            o0.y = u * f0.y * va.y;
            o0.z = u * f1.x * va.z;
            o0.w = u * f1.y * va.w;
            o1.x = u * f2.x * vb.x;
            o1.y = u * f2.y * vb.y;
            o1.z = u * f3.x * vb.z;
            o1.w = u * f3.y * vb.w;
            __stcs(Ow + 2 * i,     o0);
            __stcs(Ow + 2 * i + 1, o1);
        }
    }
}

// ---------------------------------------------------------------------------
extern "C" void kernel_launch(void* const* d_in, const int* in_sizes, int n_in,
                              void* d_out, int out_size) {
    const float* cost = (const float*)d_in[0];
    const float* src  = (const float*)d_in[1];
    const float* tgt  = (const float*)d_in[2];
    float* out = (float*)d_out;

    initKernel<<<1, 256>>>();
    sinkhornKernel<<<GRID, TPB>>>(cost, src, tgt, out);
}